// round 2
// baseline (speedup 1.0000x reference)
#include <cuda_runtime.h>
#include <math.h>

#define MAXR 8192
__device__ int g_level[MAXR];
__device__ int g_pos[MAXR];

// ---------------------------------------------------------------------------
// Prolog (fused): compute per-ROI FPN level AND stable-sort rank.
// Every block recomputes all R levels into shared memory (cheap: ~16 log2f per
// thread), then computes the stable rank for its own slice of ROIs.
//   pos[r] = #{j: lvl[j]<lvl[r]} + #{j<r: lvl[j]==lvl[r]}
// ---------------------------------------------------------------------------
__global__ void k_prolog(const float* __restrict__ rois,
                         const int* __restrict__ ih, const int* __restrict__ iw,
                         int R)
{
    __shared__ int slv[MAXR];

    float area  = (float)((*ih) * (*iw));
    float canon = 224.0f / sqrtf(area);

    for (int j = threadIdx.x; j < R; j += blockDim.x) {
        float y1 = rois[4 * j + 0];
        float x1 = rois[4 * j + 1];
        float y2 = rois[4 * j + 2];
        float x2 = rois[4 * j + 3];
        float hw = (y2 - y1) * (x2 - x1);
        float spec = log2f(sqrtf(fmaxf(hw, 1e-12f)) / canon);
        int lvl = 4 + (int)rintf(spec);
        slv[j] = lvl < 2 ? 2 : (lvl > 5 ? 5 : lvl);
    }
    __syncthreads();

    int r = blockIdx.x * blockDim.x + threadIdx.x;
    if (r >= R) return;
    int myl = slv[r];
    int pos = 0;
    for (int j = 0; j < R; ++j) {
        int lj = slv[j];
        pos += (int)((lj < myl) | ((lj == myl) & (j < r)));
    }
    g_pos[r]   = pos;
    g_level[r] = myl;
}

// ---------------------------------------------------------------------------
// Main: bilinear crop-and-resize gather.
// One 64-thread block per (roi, py, px); thread t handles channels 4t..4t+3.
// Each tap is a contiguous, 1KB-aligned NHWC row segment -> fully coalesced.
// Output written with streaming (.cs) stores so the 100MB of writes do not
// evict the feature-map tap working set from L2.
// ---------------------------------------------------------------------------
__global__ void k_roialign(const float* __restrict__ rois,
                           const float* __restrict__ p2,
                           const float* __restrict__ p3,
                           const float* __restrict__ p4,
                           const float* __restrict__ p5,
                           float* __restrict__ out,
                           int R, int N, int C)
{
    int blk  = blockIdx.x;
    int r    = blk / 49;
    int cell = blk - r * 49;
    int py   = cell / 7;
    int px   = cell - py * 7;
    int lane = threadIdx.x;            // 0 .. C/4-1

    float4 box = __ldg((const float4*)(rois + 4 * r));
    float y1 = box.x, x1 = box.y, y2 = box.z, x2 = box.w;

    int lvl = g_level[r];
    int pos = g_pos[r];
    int b   = r / N;

    const float* feat;
    int H;
    switch (lvl) {
        case 2:  feat = p2; H = 256; break;
        case 3:  feat = p3; H = 128; break;
        case 4:  feat = p4; H = 64;  break;
        default: feat = p5; H = 32;  break;
    }
    int W = H;

    const float inv6 = 1.0f / 6.0f;
    float fy = (float)py * inv6;
    float fx = (float)px * inv6;
    float in_y = (y1 + fy * (y2 - y1)) * (float)(H - 1);
    float in_x = (x1 + fx * (x2 - x1)) * (float)(W - 1);

    float y0f = floorf(in_y);
    float x0f = floorf(in_x);
    float wy = in_y - y0f;
    float wx = in_x - x0f;
    int y0 = (int)y0f;
    int x0 = (int)x0f;
    int y0c = min(max(y0,     0), H - 1);
    int y1c = min(max(y0 + 1, 0), H - 1);
    int x0c = min(max(x0,     0), W - 1);
    int x1c = min(max(x0 + 1, 0), W - 1);

    bool valid = (in_y >= 0.0f) && (in_y <= (float)(H - 1)) &&
                 (in_x >= 0.0f) && (in_x <= (float)(W - 1));
    float vm = valid ? 1.0f : 0.0f;

    int base = b * H * W;
    const float4* f00 = (const float4*)(feat + (long long)(base + y0c * W + x0c) * C);
    const float4* f01 = (const float4*)(feat + (long long)(base + y0c * W + x1c) * C);
    const float4* f10 = (const float4*)(feat + (long long)(base + y1c * W + x0c) * C);
    const float4* f11 = (const float4*)(feat + (long long)(base + y1c * W + x1c) * C);

    float4 v00 = __ldg(&f00[lane]);
    float4 v01 = __ldg(&f01[lane]);
    float4 v10 = __ldg(&f10[lane]);
    float4 v11 = __ldg(&f11[lane]);

    float owx = 1.0f - wx;
    float owy = 1.0f - wy;

    float4 res;
    res.x = ((v00.x * owx + v01.x * wx) * owy + (v10.x * owx + v11.x * wx) * wy) * vm;
    res.y = ((v00.y * owx + v01.y * wx) * owy + (v10.y * owx + v11.y * wx) * wy) * vm;
    res.z = ((v00.z * owx + v01.z * wx) * owy + (v10.z * owx + v11.z * wx) * wy) * vm;
    res.w = ((v00.w * owx + v01.w * wx) * owy + (v10.w * owx + v11.w * wx) * wy) * vm;

    // Streaming store: evict-first so output traffic doesn't thrash L2.
    __stcs((float4*)(out + (long long)(pos * 49 + cell) * C) + lane, res);
}

// ---------------------------------------------------------------------------
// Inputs (metadata order): rois [B*N*4] f32, image_h [1] i32, image_w [1] i32,
//                          p2, p3, p4, p5 (NHWC f32). Output: [R,7,7,C] f32.
// ---------------------------------------------------------------------------
extern "C" void kernel_launch(void* const* d_in, const int* in_sizes, int n_in,
                              void* d_out, int out_size)
{
    const float* rois = (const float*)d_in[0];
    const int*   ih   = (const int*)d_in[1];
    const int*   iw   = (const int*)d_in[2];
    const float* p2   = (const float*)d_in[3];
    const float* p3   = (const float*)d_in[4];
    const float* p4   = (const float*)d_in[5];
    const float* p5   = (const float*)d_in[6];
    float* out = (float*)d_out;

    int R = in_sizes[0] / 4;
    int C = 256;
    int B = in_sizes[3] / (256 * 256 * C);   // p2 is [B,256,256,256]
    if (B < 1) B = 1;
    int N = R / B;

    int threads = 128;
    int blocks  = (R + threads - 1) / threads;
    k_prolog<<<blocks, threads>>>(rois, ih, iw, R);
    k_roialign<<<R * 49, C / 4>>>(rois, p2, p3, p4, p5, out, R, N, C);
}

// round 3
// speedup vs baseline: 1.2827x; 1.2827x over previous
#include <cuda_runtime.h>
#include <math.h>

#define MAXR 8192
__device__ int g_level[MAXR];
__device__ int g_pos[MAXR];

// ---------------------------------------------------------------------------
// Prolog: per-ROI FPN level + stable-sort rank (fused).
//   pos[r] = #{j: lvl[j]<lvl[r]} + #{j<r: lvl[j]==lvl[r]}
// ---------------------------------------------------------------------------
__global__ void k_prolog(const float* __restrict__ rois,
                         const int* __restrict__ ih, const int* __restrict__ iw,
                         int R)
{
    __shared__ int slv[MAXR];

    float area  = (float)((*ih) * (*iw));
    float canon = 224.0f / sqrtf(area);

    for (int j = threadIdx.x; j < R; j += blockDim.x) {
        float y1 = rois[4 * j + 0];
        float x1 = rois[4 * j + 1];
        float y2 = rois[4 * j + 2];
        float x2 = rois[4 * j + 3];
        float hw = (y2 - y1) * (x2 - x1);
        float spec = log2f(sqrtf(fmaxf(hw, 1e-12f)) / canon);
        int lvl = 4 + (int)rintf(spec);
        slv[j] = lvl < 2 ? 2 : (lvl > 5 ? 5 : lvl);
    }
    __syncthreads();

    int r = blockIdx.x * blockDim.x + threadIdx.x;
    if (r >= R) return;
    int myl = slv[r];
    int pos = 0;
    for (int j = 0; j < R; ++j) {
        int lj = slv[j];
        pos += (int)((lj < myl) | ((lj == myl) & (j < r)));
    }
    g_pos[r]   = pos;
    g_level[r] = myl;
}

// ---------------------------------------------------------------------------
// Main: one 256-thread block per ROI.
// Threads 0..48 compute per-cell tap offsets/weights ONCE into smem; then all
// threads sweep the 49 cells (4 cells in flight, lane = float4 channel chunk).
// Each tap read / cell write is a contiguous 1KB NHWC segment -> coalesced.
// ---------------------------------------------------------------------------
struct CellP {
    int   o00, o01, o10, o11;   // float4-granular element offsets into feat
    float wx, wy, vm;
};

__global__ __launch_bounds__(256) void k_roialign(
                           const float* __restrict__ rois,
                           const float* __restrict__ p2,
                           const float* __restrict__ p3,
                           const float* __restrict__ p4,
                           const float* __restrict__ p5,
                           float* __restrict__ out,
                           int N)
{
    __shared__ CellP cp[49];
    __shared__ const float4* s_feat;

    int r    = blockIdx.x;
    int tid  = threadIdx.x;
    int lane = tid & 63;        // float4 channel chunk 0..63 (256 ch)
    int cgrp = tid >> 6;        // 0..3

    int lvl = g_level[r];
    int pos = g_pos[r];
    int b   = r / N;

    if (tid < 49) {
        const float* feat;
        int H;
        switch (lvl) {
            case 2:  feat = p2; H = 256; break;
            case 3:  feat = p3; H = 128; break;
            case 4:  feat = p4; H = 64;  break;
            default: feat = p5; H = 32;  break;
        }
        int W = H;
        if (tid == 0) s_feat = (const float4*)feat;

        float4 box = __ldg((const float4*)(rois + 4 * r));
        float y1 = box.x, x1 = box.y, y2 = box.z, x2 = box.w;

        int py = tid / 7;
        int px = tid - py * 7;
        const float inv6 = 1.0f / 6.0f;
        float in_y = (y1 + (float)py * inv6 * (y2 - y1)) * (float)(H - 1);
        float in_x = (x1 + (float)px * inv6 * (x2 - x1)) * (float)(W - 1);

        float y0f = floorf(in_y);
        float x0f = floorf(in_x);
        int y0 = (int)y0f;
        int x0 = (int)x0f;
        int y0c = min(max(y0,     0), H - 1);
        int y1c = min(max(y0 + 1, 0), H - 1);
        int x0c = min(max(x0,     0), W - 1);
        int x1c = min(max(x0 + 1, 0), W - 1);

        bool valid = (in_y >= 0.0f) && (in_y <= (float)(H - 1)) &&
                     (in_x >= 0.0f) && (in_x <= (float)(W - 1));

        int base = b * H * W;
        // offsets in float4 units: elem_index * C / 4 = elem_index * 64
        cp[tid].o00 = (base + y0c * W + x0c) * 64;
        cp[tid].o01 = (base + y0c * W + x1c) * 64;
        cp[tid].o10 = (base + y1c * W + x0c) * 64;
        cp[tid].o11 = (base + y1c * W + x1c) * 64;
        cp[tid].wx  = in_x - x0f;
        cp[tid].wy  = in_y - y0f;
        cp[tid].vm  = valid ? 1.0f : 0.0f;
    }
    __syncthreads();

    const float4* feat4 = s_feat;
    float4* out4 = (float4*)out + (long long)pos * 49 * 64 + lane;

    #pragma unroll
    for (int cell = cgrp; cell < 49; cell += 4) {
        CellP p = cp[cell];

        float4 v00 = __ldg(feat4 + p.o00 + lane);
        float4 v01 = __ldg(feat4 + p.o01 + lane);
        float4 v10 = __ldg(feat4 + p.o10 + lane);
        float4 v11 = __ldg(feat4 + p.o11 + lane);

        float wx = p.wx, wy = p.wy, vm = p.vm;
        float owx = 1.0f - wx;
        float owy = 1.0f - wy;

        float4 res;
        res.x = ((v00.x * owx + v01.x * wx) * owy + (v10.x * owx + v11.x * wx) * wy) * vm;
        res.y = ((v00.y * owx + v01.y * wx) * owy + (v10.y * owx + v11.y * wx) * wy) * vm;
        res.z = ((v00.z * owx + v01.z * wx) * owy + (v10.z * owx + v11.z * wx) * wy) * vm;
        res.w = ((v00.w * owx + v01.w * wx) * owy + (v10.w * owx + v11.w * wx) * wy) * vm;

        out4[cell * 64] = res;
    }
}

// ---------------------------------------------------------------------------
// Inputs (metadata order): rois [B*N*4] f32, image_h [1] i32, image_w [1] i32,
//                          p2, p3, p4, p5 (NHWC f32). Output: [R,7,7,C] f32.
// ---------------------------------------------------------------------------
extern "C" void kernel_launch(void* const* d_in, const int* in_sizes, int n_in,
                              void* d_out, int out_size)
{
    const float* rois = (const float*)d_in[0];
    const int*   ih   = (const int*)d_in[1];
    const int*   iw   = (const int*)d_in[2];
    const float* p2   = (const float*)d_in[3];
    const float* p3   = (const float*)d_in[4];
    const float* p4   = (const float*)d_in[5];
    const float* p5   = (const float*)d_in[6];
    float* out = (float*)d_out;

    int R = in_sizes[0] / 4;
    int C = 256;
    int B = in_sizes[3] / (256 * 256 * C);   // p2 is [B,256,256,256]
    if (B < 1) B = 1;
    int N = R / B;

    int threads = 128;
    int blocks  = (R + threads - 1) / threads;
    k_prolog<<<blocks, threads>>>(rois, ih, iw, R);
    k_roialign<<<R, 256>>>(rois, p2, p3, p4, p5, out, N);
}

// round 4
// speedup vs baseline: 1.6637x; 1.2971x over previous
#include <cuda_runtime.h>
#include <math.h>

#define MAXR 4096   // R = B*N = 2000 for this problem; smem table sized 16KB

struct CellP {
    int   o00, o01, o10, o11;   // float4-granular element offsets into feat
    float wx, wy, vm;
};

// ---------------------------------------------------------------------------
// Single fused kernel: one 256-thread block per ROI.
//  Phase A: all threads cooperatively compute FPN levels for ALL R ROIs into
//           smem (8/thread), then each thread counts its slice of the stable
//           rank indicator; block-reduce -> pos (output row for this ROI).
//  Phase B: threads 0..48 compute per-cell tap offsets/weights into smem.
//  Phase C: all threads sweep the 49 cells (lane = float4 channel chunk,
//           4 cells in flight). Taps/writes are contiguous 1KB NHWC segments.
// ---------------------------------------------------------------------------
__global__ __launch_bounds__(256) void k_fused(
                           const float* __restrict__ rois,
                           const int* __restrict__ ih, const int* __restrict__ iw,
                           const float* __restrict__ p2,
                           const float* __restrict__ p3,
                           const float* __restrict__ p4,
                           const float* __restrict__ p5,
                           float* __restrict__ out,
                           int R, int N)
{
    __shared__ int   slv[MAXR];
    __shared__ int   sred[8];
    __shared__ CellP cp[49];
    __shared__ const float4* s_feat;

    int r    = blockIdx.x;
    int tid  = threadIdx.x;
    int lane = tid & 63;        // float4 channel chunk 0..63 (256 ch)
    int cgrp = tid >> 6;        // 0..3

    // ---- Phase A: levels for all ROIs + stable rank of ROI r ----
    float area  = (float)((*ih) * (*iw));
    float canon = 224.0f / sqrtf(area);

    for (int j = tid; j < R; j += 256) {
        float4 bx = __ldg((const float4*)(rois + 4 * j));
        float hw = (bx.z - bx.x) * (bx.w - bx.y);
        float spec = log2f(sqrtf(fmaxf(hw, 1e-12f)) / canon);
        int lvl = 4 + (int)rintf(spec);
        slv[j] = lvl < 2 ? 2 : (lvl > 5 ? 5 : lvl);
    }
    __syncthreads();

    int myl = slv[r];
    int cnt = 0;
    for (int j = tid; j < R; j += 256) {
        int lj = slv[j];
        cnt += (int)((lj < myl) | ((lj == myl) & (j < r)));
    }
    cnt = __reduce_add_sync(0xffffffff, cnt);
    if ((tid & 31) == 0) sred[tid >> 5] = cnt;
    __syncthreads();
    int pos = sred[0] + sred[1] + sred[2] + sred[3] +
              sred[4] + sred[5] + sred[6] + sred[7];

    // ---- Phase B: per-cell tap parameters (once per ROI) ----
    if (tid < 49) {
        const float* feat;
        int H;
        switch (myl) {
            case 2:  feat = p2; H = 256; break;
            case 3:  feat = p3; H = 128; break;
            case 4:  feat = p4; H = 64;  break;
            default: feat = p5; H = 32;  break;
        }
        int W = H;
        if (tid == 0) s_feat = (const float4*)feat;

        float4 box = __ldg((const float4*)(rois + 4 * r));
        float y1 = box.x, x1 = box.y, y2 = box.z, x2 = box.w;

        int py = tid / 7;
        int px = tid - py * 7;
        const float inv6 = 1.0f / 6.0f;
        float in_y = (y1 + (float)py * inv6 * (y2 - y1)) * (float)(H - 1);
        float in_x = (x1 + (float)px * inv6 * (x2 - x1)) * (float)(W - 1);

        float y0f = floorf(in_y);
        float x0f = floorf(in_x);
        int y0 = (int)y0f;
        int x0 = (int)x0f;
        int y0c = min(max(y0,     0), H - 1);
        int y1c = min(max(y0 + 1, 0), H - 1);
        int x0c = min(max(x0,     0), W - 1);
        int x1c = min(max(x0 + 1, 0), W - 1);

        bool valid = (in_y >= 0.0f) && (in_y <= (float)(H - 1)) &&
                     (in_x >= 0.0f) && (in_x <= (float)(W - 1));

        int b = r / N;
        int base = b * H * W;
        cp[tid].o00 = (base + y0c * W + x0c) * 64;   // float4 units (C/4 = 64)
        cp[tid].o01 = (base + y0c * W + x1c) * 64;
        cp[tid].o10 = (base + y1c * W + x0c) * 64;
        cp[tid].o11 = (base + y1c * W + x1c) * 64;
        cp[tid].wx  = in_x - x0f;
        cp[tid].wy  = in_y - y0f;
        cp[tid].vm  = valid ? 1.0f : 0.0f;
    }
    __syncthreads();

    // ---- Phase C: gather + bilinear blend + write ----
    const float4* feat4 = s_feat;
    float4* out4 = (float4*)out + (long long)pos * 49 * 64 + lane;

    #pragma unroll
    for (int cell = cgrp; cell < 49; cell += 4) {
        CellP p = cp[cell];

        float4 v00 = __ldg(feat4 + p.o00 + lane);
        float4 v01 = __ldg(feat4 + p.o01 + lane);
        float4 v10 = __ldg(feat4 + p.o10 + lane);
        float4 v11 = __ldg(feat4 + p.o11 + lane);

        float wx = p.wx, wy = p.wy, vm = p.vm;
        float owx = 1.0f - wx;
        float owy = 1.0f - wy;

        float4 res;
        res.x = ((v00.x * owx + v01.x * wx) * owy + (v10.x * owx + v11.x * wx) * wy) * vm;
        res.y = ((v00.y * owx + v01.y * wx) * owy + (v10.y * owx + v11.y * wx) * wy) * vm;
        res.z = ((v00.z * owx + v01.z * wx) * owy + (v10.z * owx + v11.z * wx) * wy) * vm;
        res.w = ((v00.w * owx + v01.w * wx) * owy + (v10.w * owx + v11.w * wx) * wy) * vm;

        out4[cell * 64] = res;
    }
}

// ---------------------------------------------------------------------------
// Inputs (metadata order): rois [B*N*4] f32, image_h [1] i32, image_w [1] i32,
//                          p2, p3, p4, p5 (NHWC f32). Output: [R,7,7,C] f32.
// ---------------------------------------------------------------------------
extern "C" void kernel_launch(void* const* d_in, const int* in_sizes, int n_in,
                              void* d_out, int out_size)
{
    const float* rois = (const float*)d_in[0];
    const int*   ih   = (const int*)d_in[1];
    const int*   iw   = (const int*)d_in[2];
    const float* p2   = (const float*)d_in[3];
    const float* p3   = (const float*)d_in[4];
    const float* p4   = (const float*)d_in[5];
    const float* p5   = (const float*)d_in[6];
    float* out = (float*)d_out;

    int R = in_sizes[0] / 4;
    int C = 256;
    int B = in_sizes[3] / (256 * 256 * C);   // p2 is [B,256,256,256]
    if (B < 1) B = 1;
    int N = R / B;

    k_fused<<<R, 256>>>(rois, ih, iw, p2, p3, p4, p5, out, R, N);
}

// round 5
// speedup vs baseline: 1.8954x; 1.1392x over previous
#include <cuda_runtime.h>
#include <math.h>

#define MAXR 4096
__device__ int g_level[MAXR];
__device__ int g_pos[MAXR];

// ---------------------------------------------------------------------------
// Prolog: single 1024-thread block. Each thread owns 2 consecutive ROIs.
// Level = clip(4 + round(log2(sqrt(hw)*sqrt(area)/224)), 2, 5).
// Stable rank via packed counting scan: 4 levels x 16-bit counters in a u64,
// one block-wide exclusive scan -> pos[r] = base[lvl] + sameLevelPrefix[r].
// ---------------------------------------------------------------------------
__global__ __launch_bounds__(1024) void k_prolog(
        const float* __restrict__ rois,
        const int* __restrict__ ih, const int* __restrict__ iw,
        int R)
{
    __shared__ unsigned long long wsum[32];

    int tid  = threadIdx.x;
    int lane = tid & 31;
    int wid  = tid >> 5;
    int e0 = 2 * tid;
    int e1 = 2 * tid + 1;

    float area  = (float)((*ih) * (*iw));
    float canon = 224.0f / sqrtf(area);

    int lvl0 = 2, lvl1 = 2;
    unsigned long long d0 = 0, d1 = 0;
    if (e0 < R) {
        float4 bx = __ldg((const float4*)(rois + 4 * e0));
        float hw = (bx.z - bx.x) * (bx.w - bx.y);
        int l = 4 + (int)rintf(log2f(sqrtf(fmaxf(hw, 1e-12f)) / canon));
        lvl0 = l < 2 ? 2 : (l > 5 ? 5 : l);
        d0 = 1ULL << (16 * (lvl0 - 2));
    }
    if (e1 < R) {
        float4 bx = __ldg((const float4*)(rois + 4 * e1));
        float hw = (bx.z - bx.x) * (bx.w - bx.y);
        int l = 4 + (int)rintf(log2f(sqrtf(fmaxf(hw, 1e-12f)) / canon));
        lvl1 = l < 2 ? 2 : (l > 5 ? 5 : l);
        d1 = 1ULL << (16 * (lvl1 - 2));
    }

    unsigned long long pair = d0 + d1;

    // inclusive warp scan
    unsigned long long incl = pair;
    #pragma unroll
    for (int s = 1; s < 32; s <<= 1) {
        unsigned long long up = __shfl_up_sync(0xffffffff, incl, s);
        if (lane >= s) incl += up;
    }
    if (lane == 31) wsum[wid] = incl;
    __syncthreads();

    if (wid == 0) {
        unsigned long long v = wsum[lane];
        unsigned long long iv = v;
        #pragma unroll
        for (int s = 1; s < 32; s <<= 1) {
            unsigned long long up = __shfl_up_sync(0xffffffff, iv, s);
            if (lane >= s) iv += up;
        }
        wsum[lane] = iv;
    }
    __syncthreads();

    unsigned long long total = wsum[31];
    unsigned long long excl  = incl - pair + (wid > 0 ? wsum[wid - 1] : 0ULL);

    // base offsets: #elements with strictly smaller level
    int cnt2 = (int)(total & 0xffff);
    int cnt3 = (int)((total >> 16) & 0xffff);
    int cnt4 = (int)((total >> 32) & 0xffff);
    int base[4];
    base[0] = 0;
    base[1] = cnt2;
    base[2] = cnt2 + cnt3;
    base[3] = cnt2 + cnt3 + cnt4;

    if (e0 < R) {
        int same = (int)((excl >> (16 * (lvl0 - 2))) & 0xffff);
        g_level[e0] = lvl0;
        g_pos[e0]   = base[lvl0 - 2] + same;
    }
    if (e1 < R) {
        unsigned long long excl1 = excl + d0;
        int same = (int)((excl1 >> (16 * (lvl1 - 2))) & 0xffff);
        g_level[e1] = lvl1;
        g_pos[e1]   = base[lvl1 - 2] + same;
    }
}

// ---------------------------------------------------------------------------
// Main: one 256-thread block per ROI.
// Threads 0..48 compute per-cell tap offsets/weights ONCE into smem; then all
// threads sweep the 49 cells (4 cells in flight, lane = float4 channel chunk).
// Each tap read / cell write is a contiguous 1KB NHWC segment -> coalesced.
// ---------------------------------------------------------------------------
struct CellP {
    int   o00, o01, o10, o11;   // float4-granular element offsets into feat
    float wx, wy, vm;
};

__global__ __launch_bounds__(256) void k_roialign(
                           const float* __restrict__ rois,
                           const float* __restrict__ p2,
                           const float* __restrict__ p3,
                           const float* __restrict__ p4,
                           const float* __restrict__ p5,
                           float* __restrict__ out,
                           int N)
{
    __shared__ CellP cp[49];
    __shared__ const float4* s_feat;

    int r    = blockIdx.x;
    int tid  = threadIdx.x;
    int lane = tid & 63;        // float4 channel chunk 0..63 (256 ch)
    int cgrp = tid >> 6;        // 0..3

    int lvl = g_level[r];
    int pos = g_pos[r];
    int b   = r / N;

    if (tid < 49) {
        const float* feat;
        int H;
        switch (lvl) {
            case 2:  feat = p2; H = 256; break;
            case 3:  feat = p3; H = 128; break;
            case 4:  feat = p4; H = 64;  break;
            default: feat = p5; H = 32;  break;
        }
        int W = H;
        if (tid == 0) s_feat = (const float4*)feat;

        float4 box = __ldg((const float4*)(rois + 4 * r));
        float y1 = box.x, x1 = box.y, y2 = box.z, x2 = box.w;

        int py = tid / 7;
        int px = tid - py * 7;
        const float inv6 = 1.0f / 6.0f;
        float in_y = (y1 + (float)py * inv6 * (y2 - y1)) * (float)(H - 1);
        float in_x = (x1 + (float)px * inv6 * (x2 - x1)) * (float)(W - 1);

        float y0f = floorf(in_y);
        float x0f = floorf(in_x);
        int y0 = (int)y0f;
        int x0 = (int)x0f;
        int y0c = min(max(y0,     0), H - 1);
        int y1c = min(max(y0 + 1, 0), H - 1);
        int x0c = min(max(x0,     0), W - 1);
        int x1c = min(max(x0 + 1, 0), W - 1);

        bool valid = (in_y >= 0.0f) && (in_y <= (float)(H - 1)) &&
                     (in_x >= 0.0f) && (in_x <= (float)(W - 1));

        int base = b * H * W;
        cp[tid].o00 = (base + y0c * W + x0c) * 64;   // float4 units (C/4 = 64)
        cp[tid].o01 = (base + y0c * W + x1c) * 64;
        cp[tid].o10 = (base + y1c * W + x0c) * 64;
        cp[tid].o11 = (base + y1c * W + x1c) * 64;
        cp[tid].wx  = in_x - x0f;
        cp[tid].wy  = in_y - y0f;
        cp[tid].vm  = valid ? 1.0f : 0.0f;
    }
    __syncthreads();

    const float4* feat4 = s_feat;
    float4* out4 = (float4*)out + (long long)pos * 49 * 64 + lane;

    #pragma unroll
    for (int cell = cgrp; cell < 49; cell += 4) {
        CellP p = cp[cell];

        float4 v00 = __ldg(feat4 + p.o00 + lane);
        float4 v01 = __ldg(feat4 + p.o01 + lane);
        float4 v10 = __ldg(feat4 + p.o10 + lane);
        float4 v11 = __ldg(feat4 + p.o11 + lane);

        float wx = p.wx, wy = p.wy, vm = p.vm;
        float owx = 1.0f - wx;
        float owy = 1.0f - wy;

        float4 res;
        res.x = ((v00.x * owx + v01.x * wx) * owy + (v10.x * owx + v11.x * wx) * wy) * vm;
        res.y = ((v00.y * owx + v01.y * wx) * owy + (v10.y * owx + v11.y * wx) * wy) * vm;
        res.z = ((v00.z * owx + v01.z * wx) * owy + (v10.z * owx + v11.z * wx) * wy) * vm;
        res.w = ((v00.w * owx + v01.w * wx) * owy + (v10.w * owx + v11.w * wx) * wy) * vm;

        out4[cell * 64] = res;
    }
}

// ---------------------------------------------------------------------------
// Inputs (metadata order): rois [B*N*4] f32, image_h [1] i32, image_w [1] i32,
//                          p2, p3, p4, p5 (NHWC f32). Output: [R,7,7,C] f32.
// ---------------------------------------------------------------------------
extern "C" void kernel_launch(void* const* d_in, const int* in_sizes, int n_in,
                              void* d_out, int out_size)
{
    const float* rois = (const float*)d_in[0];
    const int*   ih   = (const int*)d_in[1];
    const int*   iw   = (const int*)d_in[2];
    const float* p2   = (const float*)d_in[3];
    const float* p3   = (const float*)d_in[4];
    const float* p4   = (const float*)d_in[5];
    const float* p5   = (const float*)d_in[6];
    float* out = (float*)d_out;

    int R = in_sizes[0] / 4;
    int C = 256;
    int B = in_sizes[3] / (256 * 256 * C);   // p2 is [B,256,256,256]
    if (B < 1) B = 1;
    int N = R / B;

    k_prolog<<<1, 1024>>>(rois, ih, iw, R);
    k_roialign<<<R, 256>>>(rois, p2, p3, p4, p5, out, N);
}

// round 6
// speedup vs baseline: 1.9984x; 1.0543x over previous
#include <cuda_runtime.h>
#include <math.h>

#define MAXR 4096
__device__ int g_level[MAXR];
__device__ int g_pos[MAXR];

// ---------------------------------------------------------------------------
// Prolog: single 1024-thread block. Each thread owns 2 consecutive ROIs.
// Stable rank via packed counting scan: 4 levels x 16-bit counters in a u64.
// ---------------------------------------------------------------------------
__global__ __launch_bounds__(1024) void k_prolog(
        const float* __restrict__ rois,
        const int* __restrict__ ih, const int* __restrict__ iw,
        int R)
{
    __shared__ unsigned long long wsum[32];

    int tid  = threadIdx.x;
    int lane = tid & 31;
    int wid  = tid >> 5;
    int e0 = 2 * tid;
    int e1 = 2 * tid + 1;

    float area  = (float)((*ih) * (*iw));
    float canon = 224.0f / sqrtf(area);

    int lvl0 = 2, lvl1 = 2;
    unsigned long long d0 = 0, d1 = 0;
    if (e0 < R) {
        float4 bx = __ldg((const float4*)(rois + 4 * e0));
        float hw = (bx.z - bx.x) * (bx.w - bx.y);
        int l = 4 + (int)rintf(log2f(sqrtf(fmaxf(hw, 1e-12f)) / canon));
        lvl0 = l < 2 ? 2 : (l > 5 ? 5 : l);
        d0 = 1ULL << (16 * (lvl0 - 2));
    }
    if (e1 < R) {
        float4 bx = __ldg((const float4*)(rois + 4 * e1));
        float hw = (bx.z - bx.x) * (bx.w - bx.y);
        int l = 4 + (int)rintf(log2f(sqrtf(fmaxf(hw, 1e-12f)) / canon));
        lvl1 = l < 2 ? 2 : (l > 5 ? 5 : l);
        d1 = 1ULL << (16 * (lvl1 - 2));
    }

    unsigned long long pair = d0 + d1;
    unsigned long long incl = pair;
    #pragma unroll
    for (int s = 1; s < 32; s <<= 1) {
        unsigned long long up = __shfl_up_sync(0xffffffff, incl, s);
        if (lane >= s) incl += up;
    }
    if (lane == 31) wsum[wid] = incl;
    __syncthreads();
    if (wid == 0) {
        unsigned long long iv = wsum[lane];
        #pragma unroll
        for (int s = 1; s < 32; s <<= 1) {
            unsigned long long up = __shfl_up_sync(0xffffffff, iv, s);
            if (lane >= s) iv += up;
        }
        wsum[lane] = iv;
    }
    __syncthreads();

    unsigned long long total = wsum[31];
    unsigned long long excl  = incl - pair + (wid > 0 ? wsum[wid - 1] : 0ULL);

    int cnt2 = (int)(total & 0xffff);
    int cnt3 = (int)((total >> 16) & 0xffff);
    int cnt4 = (int)((total >> 32) & 0xffff);
    int base[4];
    base[0] = 0;
    base[1] = cnt2;
    base[2] = cnt2 + cnt3;
    base[3] = cnt2 + cnt3 + cnt4;

    if (e0 < R) {
        int same = (int)((excl >> (16 * (lvl0 - 2))) & 0xffff);
        g_level[e0] = lvl0;
        g_pos[e0]   = base[lvl0 - 2] + same;
    }
    if (e1 < R) {
        unsigned long long excl1 = excl + d0;
        int same = (int)((excl1 >> (16 * (lvl1 - 2))) & 0xffff);
        g_level[e1] = lvl1;
        g_pos[e1]   = base[lvl1 - 2] + same;
    }
}

// ---------------------------------------------------------------------------
// Main: one 256-thread block per ROI. Cell params in SoA smem (int4 offsets +
// float4 weights -> LDS.128). Cell loop unrolled x2: 8 independent LDG.128 in
// flight per thread before any blend (latency hiding via per-thread MLP).
// ---------------------------------------------------------------------------
__global__ __launch_bounds__(256) void k_roialign(
                           const float* __restrict__ rois,
                           const float* __restrict__ p2,
                           const float* __restrict__ p3,
                           const float* __restrict__ p4,
                           const float* __restrict__ p5,
                           float* __restrict__ out,
                           int N)
{
    __shared__ int4   soff[49];   // o00,o01,o10,o11 (float4 units)
    __shared__ float4 swgt[49];   // wx, wy, vm, pad
    __shared__ const float4* s_feat;

    int r    = blockIdx.x;
    int tid  = threadIdx.x;
    int lane = tid & 63;        // float4 channel chunk 0..63 (256 ch)
    int cgrp = tid >> 6;        // 0..3

    if (tid < 49) {
        int lvl = g_level[r];
        const float* feat;
        int H;
        switch (lvl) {
            case 2:  feat = p2; H = 256; break;
            case 3:  feat = p3; H = 128; break;
            case 4:  feat = p4; H = 64;  break;
            default: feat = p5; H = 32;  break;
        }
        int W = H;
        if (tid == 0) s_feat = (const float4*)feat;

        float4 box = __ldg((const float4*)(rois + 4 * r));
        float y1 = box.x, x1 = box.y, y2 = box.z, x2 = box.w;

        int py = tid / 7;
        int px = tid - py * 7;
        const float inv6 = 1.0f / 6.0f;
        float in_y = (y1 + (float)py * inv6 * (y2 - y1)) * (float)(H - 1);
        float in_x = (x1 + (float)px * inv6 * (x2 - x1)) * (float)(W - 1);

        float y0f = floorf(in_y);
        float x0f = floorf(in_x);
        int y0 = (int)y0f;
        int x0 = (int)x0f;
        int y0c = min(max(y0,     0), H - 1);
        int y1c = min(max(y0 + 1, 0), H - 1);
        int x0c = min(max(x0,     0), W - 1);
        int x1c = min(max(x0 + 1, 0), W - 1);

        bool valid = (in_y >= 0.0f) && (in_y <= (float)(H - 1)) &&
                     (in_x >= 0.0f) && (in_x <= (float)(W - 1));

        int b = r / N;
        int base = b * H * W;
        int4 o;
        o.x = (base + y0c * W + x0c) * 64;
        o.y = (base + y0c * W + x1c) * 64;
        o.z = (base + y1c * W + x0c) * 64;
        o.w = (base + y1c * W + x1c) * 64;
        soff[tid] = o;
        swgt[tid] = make_float4(in_x - x0f, in_y - y0f, valid ? 1.0f : 0.0f, 0.0f);
    }
    __syncthreads();

    const float4* feat4 = s_feat;
    int pos = g_pos[r];
    float4* out4 = (float4*)out + (long long)pos * 49 * 64 + lane;

    // 49 cells: cgrp handles {cgrp+8k, cgrp+4+8k} k=0..5 (48 cells), cgrp 0
    // also handles cell 48 as epilogue.
    #pragma unroll
    for (int k = 0; k < 6; ++k) {
        int ca = cgrp + 8 * k;
        int cb = ca + 4;

        int4   oa = soff[ca];
        int4   ob = soff[cb];

        float4 a00 = __ldg(feat4 + oa.x + lane);
        float4 a01 = __ldg(feat4 + oa.y + lane);
        float4 a10 = __ldg(feat4 + oa.z + lane);
        float4 a11 = __ldg(feat4 + oa.w + lane);
        float4 b00 = __ldg(feat4 + ob.x + lane);
        float4 b01 = __ldg(feat4 + ob.y + lane);
        float4 b10 = __ldg(feat4 + ob.z + lane);
        float4 b11 = __ldg(feat4 + ob.w + lane);

        float4 wa = swgt[ca];
        float4 wb = swgt[cb];

        float awx = wa.x, awy = wa.y, avm = wa.z;
        float aox = 1.0f - awx, aoy = 1.0f - awy;
        float4 ra;
        ra.x = ((a00.x * aox + a01.x * awx) * aoy + (a10.x * aox + a11.x * awx) * awy) * avm;
        ra.y = ((a00.y * aox + a01.y * awx) * aoy + (a10.y * aox + a11.y * awx) * awy) * avm;
        ra.z = ((a00.z * aox + a01.z * awx) * aoy + (a10.z * aox + a11.z * awx) * awy) * avm;
        ra.w = ((a00.w * aox + a01.w * awx) * aoy + (a10.w * aox + a11.w * awx) * awy) * avm;
        out4[ca * 64] = ra;

        float bwx = wb.x, bwy = wb.y, bvm = wb.z;
        float box_ = 1.0f - bwx, boy = 1.0f - bwy;
        float4 rb;
        rb.x = ((b00.x * box_ + b01.x * bwx) * boy + (b10.x * box_ + b11.x * bwx) * bwy) * bvm;
        rb.y = ((b00.y * box_ + b01.y * bwx) * boy + (b10.y * box_ + b11.y * bwx) * bwy) * bvm;
        rb.z = ((b00.z * box_ + b01.z * bwx) * boy + (b10.z * box_ + b11.z * bwx) * bwy) * bvm;
        rb.w = ((b00.w * box_ + b01.w * bwx) * boy + (b10.w * box_ + b11.w * bwx) * bwy) * bvm;
        out4[cb * 64] = rb;
    }

    if (cgrp == 0) {
        int4   o = soff[48];
        float4 w = swgt[48];
        float4 v00 = __ldg(feat4 + o.x + lane);
        float4 v01 = __ldg(feat4 + o.y + lane);
        float4 v10 = __ldg(feat4 + o.z + lane);
        float4 v11 = __ldg(feat4 + o.w + lane);
        float wx = w.x, wy = w.y, vm = w.z;
        float owx = 1.0f - wx, owy = 1.0f - wy;
        float4 res;
        res.x = ((v00.x * owx + v01.x * wx) * owy + (v10.x * owx + v11.x * wx) * wy) * vm;
        res.y = ((v00.y * owx + v01.y * wx) * owy + (v10.y * owx + v11.y * wx) * wy) * vm;
        res.z = ((v00.z * owx + v01.z * wx) * owy + (v10.z * owx + v11.z * wx) * wy) * vm;
        res.w = ((v00.w * owx + v01.w * wx) * owy + (v10.w * owx + v11.w * wx) * wy) * vm;
        out4[48 * 64] = res;
    }
}

// ---------------------------------------------------------------------------
// Inputs (metadata order): rois [B*N*4] f32, image_h [1] i32, image_w [1] i32,
//                          p2, p3, p4, p5 (NHWC f32). Output: [R,7,7,C] f32.
// ---------------------------------------------------------------------------
extern "C" void kernel_launch(void* const* d_in, const int* in_sizes, int n_in,
                              void* d_out, int out_size)
{
    const float* rois = (const float*)d_in[0];
    const int*   ih   = (const int*)d_in[1];
    const int*   iw   = (const int*)d_in[2];
    const float* p2   = (const float*)d_in[3];
    const float* p3   = (const float*)d_in[4];
    const float* p4   = (const float*)d_in[5];
    const float* p5   = (const float*)d_in[6];
    float* out = (float*)d_out;

    int R = in_sizes[0] / 4;
    int C = 256;
    int B = in_sizes[3] / (256 * 256 * C);   // p2 is [B,256,256,256]
    if (B < 1) B = 1;
    int N = R / B;

    k_prolog<<<1, 1024>>>(rois, ih, iw, R);
    k_roialign<<<R, 256>>>(rois, p2, p3, p4, p5, out, N);
}